// round 9
// baseline (speedup 1.0000x reference)
#include <cuda_runtime.h>
#include <cuda_fp16.h>
#include <cstdint>

#define BB   32
#define SS   2048
#define ND   1024

// Scratch (allocation-free rule: __device__ globals)
__device__ float  g_scores[BB * SS];
__device__ float  g_decb[BB * ND];
__device__ __half g_Bth[ND * ND];         // W_enc^T fp16: Bth[n][k] = W[1024+k][n]
__device__ __half g_ench[BB * SS * ND];   // encoder_outputs in fp16

// ---------------------------------------------------------------- helpers
__device__ __forceinline__ float fast_tanh(float x) {
    float y;
    asm("tanh.approx.f32 %0, %1;" : "=f"(y) : "f"(x));
    return y;
}
__device__ __forceinline__ uint32_t smem_u32(const void* p) {
    uint32_t a;
    asm("{ .reg .u64 t; cvta.to.shared.u64 t, %1; cvt.u32.u64 %0, t; }" : "=r"(a) : "l"(p));
    return a;
}

// ---------------------------------------------------------------------------
// Kernel P: fused prologue.
//   blocks [0,8192)    : convert enc fp32 -> g_ench fp16
//   blocks [8192,9216) : transpose W_enc -> g_Bth fp16
//   blocks [9216,9344) : dec_base = dh @ W_dec + b_attn; zero scratch + ctx
// ---------------------------------------------------------------------------
__global__ void pre_kernel(const float* __restrict__ enc,
                           const float* __restrict__ W,
                           const float* __restrict__ dh,
                           const float* __restrict__ b_attn,
                           float* __restrict__ out_ctx) {
    __shared__ float shb[1088];
    const int bid = blockIdx.x;
    const int tid = threadIdx.x;

    if (bid < 8192) {
        const uint32_t t = bid * 256 + tid;
        uint2* outp = (uint2*)g_ench;
#pragma unroll
        for (int i = 0; i < 8; i++) {
            const uint32_t idx = t + (uint32_t)i * (8192 * 256);
            const float4 v = *(const float4*)(enc + (size_t)idx * 4);
            __half2 h0 = __floats2half2_rn(v.x, v.y);
            __half2 h1 = __floats2half2_rn(v.z, v.w);
            uint2 o;
            o.x = *(uint32_t*)&h0;
            o.y = *(uint32_t*)&h1;
            outp[idx] = o;
        }
    } else if (bid < 9216) {
        const int bid2 = bid - 8192;
        const int kb = (bid2 & 31) * 32, nb = (bid2 >> 5) * 32;
        const int tx = tid & 31, ty = tid >> 5;           // ty 0..7
        float (*t)[33] = (float(*)[33])shb;
#pragma unroll
        for (int i = 0; i < 32; i += 8)
            t[ty + i][tx] = W[(size_t)(1024 + kb + ty + i) * 1024 + nb + tx];
        __syncthreads();
#pragma unroll
        for (int i = 0; i < 32; i += 8)
            g_Bth[(size_t)(nb + ty + i) * 1024 + kb + tx] = __float2half_rn(t[tx][ty + i]);
    } else {
        const int bid3 = bid - 9216;                      // 0..127
        const int b = bid3 >> 2, dc = bid3 & 3;

        for (int i = bid3 * 256 + tid; i < BB * SS; i += 128 * 256) g_scores[i] = 0.f;
        for (int i = bid3 * 256 + tid; i < BB * ND; i += 128 * 256) out_ctx[i] = 0.f;

        for (int i = tid; i < ND; i += 256) shb[i] = dh[b * ND + i];
        __syncthreads();

        const int d0 = dc * 256 + tid;
        float a = b_attn[d0];
#pragma unroll 8
        for (int e = 0; e < ND; e++)
            a += shb[e] * W[(size_t)e * ND + d0];
        g_decb[b * ND + d0] = a;
    }
}

// ---------------------------------------------------------------------------
// Kernel 2: enc_proj GEMM, fp16 mma.sync m16n8k16, 128x128 tile, BK=64.
//   CTA split into TWO independent 128-thread halves (hf = tid>>7):
//     half hf owns: private A copy (128 x 64k, 16KB) + B cols [hf*64, +64) (8KB)
//     sync via named bar.sync(hf+1, 128) — no 256-thread convoy.
//   2-stage ring, per-iter order: wait_group 0 -> bar -> prefetch kt+1 ->
//   compute kt.  Safety: bar at top of iter kt releases only after all 128
//   half-threads finished compute kt-1 (which reads slot (kt-1)&1=(kt+1)&1),
//   so the prefetch of stage kt+1 into that slot is race-free; wait_group 0 +
//   bar makes every thread's stage-kt cp.asyncs visible to the whole half.
//   Panels: stage = A0(8K) A1(8K) B0(4K) B1(4K); 64B rows -> conflict-free
//   LDS.128.  K-permutation identical on A and B (exact).
// ---------------------------------------------------------------------------
#define HBLK      49152                    // bytes per half (2 stages x 24KB)
#define STOFF     24576                    // stage stride inside half
#define GEMM_SMEM (2 * HBLK)               // 96 KB

__global__ __launch_bounds__(256, 2) void score_gemm(const float* __restrict__ vw) {
    extern __shared__ char smc[];
    const uint32_t sb = smem_u32(smc);
    const int tid  = threadIdx.x;
    const int lane = tid & 31;
    const int hf   = tid >> 7;               // half id 0/1
    const int wm   = (tid >> 5) & 3;         // warp-in-half 0..3
    const int t128 = tid & 127;
    const int n0   = blockIdx.x * 128;
    const int m0   = blockIdx.y * 128;

    const uint32_t Hbase = sb + (uint32_t)hf * HBLK;

    // cp.async source pointers
    const char* srcA = (const char*)(g_ench + (size_t)(m0 + t128) * 1024);
    const int rb = t128 >> 1, cb = t128 & 1;
    const char* srcB = (const char*)(g_Bth + (size_t)(n0 + hf * 64 + rb) * 1024);
    // dst bases (stage-relative)
    const uint32_t dA = Hbase + (uint32_t)t128 * 64;              // + p*8192 + cc*16
    const uint32_t dB = Hbase + 16384 + (uint32_t)rb * 64;        // + p*4096 + ch*16

#define LOAD_STAGE(kt, st)                                                       \
    do {                                                                         \
        const uint32_t so = (uint32_t)(st) * STOFF;                              \
        const int kb_ = (kt) * 128;                                              \
        _Pragma("unroll")                                                        \
        for (int c_ = 0; c_ < 8; c_++)                                           \
            asm volatile("cp.async.cg.shared.global [%0], [%1], 16;"             \
                         :: "r"(dA + so + (c_ >> 2) * 8192 + (c_ & 3) * 16),     \
                            "l"(srcA + kb_ + c_ * 16));                          \
        _Pragma("unroll")                                                        \
        for (int p_ = 0; p_ < 2; p_++)                                           \
            _Pragma("unroll")                                                    \
            for (int i_ = 0; i_ < 2; i_++) {                                     \
                const int ch_ = cb * 2 + i_;                                     \
                asm volatile("cp.async.cg.shared.global [%0], [%1], 16;"         \
                             :: "r"(dB + so + p_ * 4096 + ch_ * 16),             \
                                "l"(srcB + kb_ + p_ * 64 + ch_ * 16));           \
            }                                                                    \
    } while (0)

    float acc[2][8][4];
#pragma unroll
    for (int i = 0; i < 2; i++)
#pragma unroll
        for (int j = 0; j < 8; j++)
#pragma unroll
            for (int c = 0; c < 4; c++) acc[i][j][c] = 0.f;

    LOAD_STAGE(0, 0);
    asm volatile("cp.async.commit_group;" ::: "memory");

    const uint32_t koff = (lane & 3) * 16;
    const uint32_t aoff = (uint32_t)(wm * 32 + (lane >> 2)) * 64 + koff;
    const uint32_t boff = (uint32_t)(lane >> 2) * 64 + koff;

#pragma unroll
    for (int kt = 0; kt < 16; kt++) {
        const int st = kt & 1;
        asm volatile("cp.async.wait_group 0;" ::: "memory");
        asm volatile("bar.sync %0, %1;" :: "r"(hf + 1), "r"(128) : "memory");

        if (kt < 15) LOAD_STAGE(kt + 1, (kt + 1) & 1);
        asm volatile("cp.async.commit_group;" ::: "memory");

        const uint32_t Astg = Hbase + (uint32_t)st * STOFF;

#pragma unroll
        for (int s = 0; s < 2; s++) {            // two k32 panels
            const uint32_t Apan = Astg + (uint32_t)s * 8192 + aoff;
            const uint32_t Bpan = Astg + 16384 + (uint32_t)s * 4096 + boff;

            uint32_t ah[4][4];
#pragma unroll
            for (int rdx = 0; rdx < 4; rdx++)
                asm volatile("ld.shared.v4.u32 {%0,%1,%2,%3}, [%4];"
                             : "=r"(ah[rdx][0]), "=r"(ah[rdx][1]),
                               "=r"(ah[rdx][2]), "=r"(ah[rdx][3])
                             : "r"(Apan + rdx * 512));

#pragma unroll
            for (int jh = 0; jh < 2; jh++) {
                uint32_t bh[4][4];
#pragma unroll
                for (int j = 0; j < 4; j++)
                    asm volatile("ld.shared.v4.u32 {%0,%1,%2,%3}, [%4];"
                                 : "=r"(bh[j][0]), "=r"(bh[j][1]),
                                   "=r"(bh[j][2]), "=r"(bh[j][3])
                                 : "r"(Bpan + (jh * 4 + j) * 512));
#pragma unroll
                for (int i = 0; i < 2; i++)
#pragma unroll
                    for (int j = 0; j < 4; j++)
#pragma unroll
                        for (int u = 0; u < 2; u++) {
                            const int jj = jh * 4 + j;
                            asm volatile(
                                "mma.sync.aligned.m16n8k16.row.col.f32.f16.f16.f32 "
                                "{%0,%1,%2,%3}, {%4,%5,%6,%7}, {%8,%9}, {%0,%1,%2,%3};"
                                : "+f"(acc[i][jj][0]), "+f"(acc[i][jj][1]),
                                  "+f"(acc[i][jj][2]), "+f"(acc[i][jj][3])
                                : "r"(ah[2 * i][2 * u]), "r"(ah[2 * i + 1][2 * u]),
                                  "r"(ah[2 * i][2 * u + 1]), "r"(ah[2 * i + 1][2 * u + 1]),
                                  "r"(bh[j][2 * u]), "r"(bh[j][2 * u + 1]));
                        }
            }
        }
    }
#undef LOAD_STAGE

    // Epilogue: energy = tanh(acc + dec_base[b][col]); score partial = energy . v_w
    const int b = m0 >> 11;
    float eadd[16], vv[16];
#pragma unroll
    for (int j = 0; j < 8; j++)
#pragma unroll
        for (int c = 0; c < 2; c++) {
            const int col = n0 + hf * 64 + j * 8 + (lane & 3) * 2 + c;
            eadd[j * 2 + c] = g_decb[b * ND + col];
            vv[j * 2 + c]   = vw[col];
        }

#pragma unroll
    for (int i = 0; i < 2; i++)
#pragma unroll
        for (int hh = 0; hh < 2; hh++) {
            float p = 0.f;
#pragma unroll
            for (int j = 0; j < 8; j++)
#pragma unroll
                for (int c = 0; c < 2; c++)
                    p += fast_tanh(acc[i][j][hh * 2 + c] + eadd[j * 2 + c]) * vv[j * 2 + c];
            p += __shfl_xor_sync(0xffffffffu, p, 1);
            p += __shfl_xor_sync(0xffffffffu, p, 2);
            if ((lane & 3) == 0) {
                const int row = m0 + wm * 32 + i * 16 + hh * 8 + (lane >> 2);
                atomicAdd(&g_scores[row], p);
            }
        }
}

// ---------------------------------------------------------------------------
// Kernel 3: masked softmax over S per batch
// ---------------------------------------------------------------------------
__global__ void softmax_kernel(const int* __restrict__ mask,
                               float* __restrict__ out_w) {
    const int b = blockIdx.x;
    const int tid = threadIdx.x;
    __shared__ float red[256];

    float ls[8];
#pragma unroll
    for (int i = 0; i < 8; i++) {
        const int s = tid + i * 256;
        const float sc = g_scores[b * SS + s];
        ls[i] = (mask[b * SS + s] == 0) ? -1e9f : sc;
    }
    float mx = ls[0];
#pragma unroll
    for (int i = 1; i < 8; i++) mx = fmaxf(mx, ls[i]);
    red[tid] = mx;
    __syncthreads();
    for (int off = 128; off > 0; off >>= 1) {
        if (tid < off) red[tid] = fmaxf(red[tid], red[tid + off]);
        __syncthreads();
    }
    mx = red[0];
    __syncthreads();

    float ex[8];
    float sum = 0.f;
#pragma unroll
    for (int i = 0; i < 8; i++) {
        ex[i] = __expf(ls[i] - mx);
        sum += ex[i];
    }
    red[tid] = sum;
    __syncthreads();
    for (int off = 128; off > 0; off >>= 1) {
        if (tid < off) red[tid] += red[tid + off];
        __syncthreads();
    }
    const float inv = 1.f / red[0];
#pragma unroll
    for (int i = 0; i < 8; i++)
        out_w[b * SS + tid + i * 256] = ex[i] * inv;
}

// ---------------------------------------------------------------------------
// Kernel 4: context = attn_weights @ encoder_outputs (fp16 enc, fp32 accum)
// ---------------------------------------------------------------------------
__global__ void context_kernel(const float* __restrict__ w,
                               float* __restrict__ ctx) {
    const int b = blockIdx.y;
    const int ch = blockIdx.x;
    const int tid = threadIdx.x;
    __shared__ float ws[128];
    const int s0 = ch * 128;
    if (tid < 128) ws[tid] = w[b * SS + s0 + tid];
    __syncthreads();

    float ax = 0.f, ay = 0.f, az = 0.f, aw = 0.f;
    const __half* base = g_ench + ((size_t)b * SS + s0) * 1024 + tid * 4;
#pragma unroll 4
    for (int s = 0; s < 128; s++) {
        const uint2 u = *(const uint2*)(base + (size_t)s * 1024);
        const float2 f01 = __half22float2(*(const __half2*)&u.x);
        const float2 f23 = __half22float2(*(const __half2*)&u.y);
        const float wv = ws[s];
        ax += wv * f01.x;
        ay += wv * f01.y;
        az += wv * f23.x;
        aw += wv * f23.y;
    }
    float* o = ctx + b * ND + tid * 4;
    atomicAdd(o + 0, ax);
    atomicAdd(o + 1, ay);
    atomicAdd(o + 2, az);
    atomicAdd(o + 3, aw);
}

// ---------------------------------------------------------------------------
extern "C" void kernel_launch(void* const* d_in, const int* in_sizes, int n_in,
                              void* d_out, int out_size) {
    const float* dh   = (const float*)d_in[0];   // (32, 1024)
    const float* enc  = (const float*)d_in[1];   // (32, 2048, 1024)
    const int*   mask = (const int*)d_in[2];     // (32, 2048)
    const float* W    = (const float*)d_in[3];   // (2048, 1024)
    const float* ba   = (const float*)d_in[4];   // (1024,)
    const float* vw   = (const float*)d_in[5];   // (1024,)

    float* out  = (float*)d_out;
    float* ctx  = out;                 // (32, 1024)
    float* attw = out + BB * ND;       // (32, 2048)

    cudaFuncSetAttribute(score_gemm, cudaFuncAttributeMaxDynamicSharedMemorySize, GEMM_SMEM);

    pre_kernel<<<9344, 256>>>(enc, W, dh, ba, ctx);
    score_gemm<<<dim3(8, 512), 256, GEMM_SMEM>>>(vw);
    softmax_kernel<<<32, 256>>>(mask, attw);
    context_kernel<<<dim3(16, 32), 256>>>(attw, ctx);
}

// round 10
// speedup vs baseline: 1.7403x; 1.7403x over previous
#include <cuda_runtime.h>
#include <cuda_fp16.h>
#include <cstdint>

#define BB   32
#define SS   2048
#define ND   1024

// Scratch (allocation-free rule: __device__ globals)
__device__ float  g_scores[BB * SS];
__device__ float  g_decb[BB * ND];
__device__ __half g_Bth[ND * ND];         // W_enc^T fp16: Bth[n][k] = W[1024+k][n]
__device__ __half g_ench[BB * SS * ND];   // encoder_outputs in fp16

// ---------------------------------------------------------------- helpers
__device__ __forceinline__ float fast_tanh(float x) {
    float y;
    asm("tanh.approx.f32 %0, %1;" : "=f"(y) : "f"(x));
    return y;
}
__device__ __forceinline__ uint32_t smem_u32(const void* p) {
    uint32_t a;
    asm("{ .reg .u64 t; cvta.to.shared.u64 t, %1; cvt.u32.u64 %0, t; }" : "=r"(a) : "l"(p));
    return a;
}

// ---------------------------------------------------------------------------
// Kernel P: fused prologue.
//   blocks [0,8192)    : convert enc fp32 -> g_ench fp16
//   blocks [8192,9216) : transpose W_enc -> g_Bth fp16
//   blocks [9216,9344) : dec_base = dh @ W_dec + b_attn; zero scratch + ctx
// ---------------------------------------------------------------------------
__global__ void pre_kernel(const float* __restrict__ enc,
                           const float* __restrict__ W,
                           const float* __restrict__ dh,
                           const float* __restrict__ b_attn,
                           float* __restrict__ out_ctx) {
    __shared__ float shb[1088];
    const int bid = blockIdx.x;
    const int tid = threadIdx.x;

    if (bid < 8192) {
        const uint32_t t = bid * 256 + tid;
        uint2* outp = (uint2*)g_ench;
#pragma unroll
        for (int i = 0; i < 8; i++) {
            const uint32_t idx = t + (uint32_t)i * (8192 * 256);
            const float4 v = *(const float4*)(enc + (size_t)idx * 4);
            __half2 h0 = __floats2half2_rn(v.x, v.y);
            __half2 h1 = __floats2half2_rn(v.z, v.w);
            uint2 o;
            o.x = *(uint32_t*)&h0;
            o.y = *(uint32_t*)&h1;
            outp[idx] = o;
        }
    } else if (bid < 9216) {
        const int bid2 = bid - 8192;
        const int kb = (bid2 & 31) * 32, nb = (bid2 >> 5) * 32;
        const int tx = tid & 31, ty = tid >> 5;           // ty 0..7
        float (*t)[33] = (float(*)[33])shb;
#pragma unroll
        for (int i = 0; i < 32; i += 8)
            t[ty + i][tx] = W[(size_t)(1024 + kb + ty + i) * 1024 + nb + tx];
        __syncthreads();
#pragma unroll
        for (int i = 0; i < 32; i += 8)
            g_Bth[(size_t)(nb + ty + i) * 1024 + kb + tx] = __float2half_rn(t[tx][ty + i]);
    } else {
        const int bid3 = bid - 9216;                      // 0..127
        const int b = bid3 >> 2, dc = bid3 & 3;

        for (int i = bid3 * 256 + tid; i < BB * SS; i += 128 * 256) g_scores[i] = 0.f;
        for (int i = bid3 * 256 + tid; i < BB * ND; i += 128 * 256) out_ctx[i] = 0.f;

        for (int i = tid; i < ND; i += 256) shb[i] = dh[b * ND + i];
        __syncthreads();

        const int d0 = dc * 256 + tid;
        float a = b_attn[d0];
#pragma unroll 8
        for (int e = 0; e < ND; e++)
            a += shb[e] * W[(size_t)e * ND + d0];
        g_decb[b * ND + d0] = a;
    }
}

// ---------------------------------------------------------------------------
// Kernel 2: enc_proj GEMM, fp16 mma.sync m16n8k16, 128x128 tile, BK=64,
//   3-stage cp.async ring (96KB), ONE sync per BK=64, FULL unroll (16 iters),
//   fused tanh + v-dot.   (R8 configuration — measured 368us, tensor 61.7%)
//   Stage layout = 4 panels of 8KB: Ak0 | Ak1 | Bk0 | Bk1. Each panel has
//   64B rows (32 halfs) -> conflict-free LDS.128 fragment loads.
//   Ring safety: sync at top of iter kt ensures stage kt-1 (slot (kt+2)%3)
//   reads are done before the loads for stage kt+2 reuse that slot.
//   Uniform commit per iter keeps wait_group 1 exact.
//   K-permutation identical on A and B (exact): thread k-window = (lane&3)*8.
// ---------------------------------------------------------------------------
#define PAN       8192
#define STGB      (4 * PAN)                // 32 KB per stage
#define GEMM_SMEM (3 * STGB)               // 96 KB

__global__ __launch_bounds__(256, 2) void score_gemm(const float* __restrict__ vw) {
    extern __shared__ char smc[];
    const uint32_t sb = smem_u32(smc);
    const int tid  = threadIdx.x;
    const int lane = tid & 31;
    const int warp = tid >> 5;
    const int wm   = warp >> 1;              // 0..3
    const int wn   = warp & 1;               // 0..1
    const int n0   = blockIdx.x * 128;
    const int m0   = blockIdx.y * 128;

    // cp.async mapping: q = tid + i*256 (i=0..3): r = tid>>3 + 32*i, c = tid&7.
    const int rr = tid >> 3, cc = tid & 7;
    const char* pa = (const char*)(g_ench + (size_t)(m0 + rr) * 1024 + cc * 8);
    const char* pb = (const char*)(g_Bth  + (size_t)(n0 + rr) * 1024 + cc * 8);
    const uint32_t dA = sb + (uint32_t)((cc >> 2) * PAN + rr * 64 + (cc & 3) * 16);
    const uint32_t dB = dA + 2 * PAN;
    // per-i increments: src += i*32 rows = i*65536 B ; dst += i*32*64 = i*2048 B

#define LOAD_STAGE(kt, st)                                                      \
    do {                                                                        \
        const uint32_t so = (uint32_t)(st) * STGB;                              \
        const int kb_ = (kt) * 128;  /* BK=64 halfs = 128 B */                  \
        _Pragma("unroll")                                                       \
        for (int i_ = 0; i_ < 4; i_++) {                                        \
            asm volatile("cp.async.cg.shared.global [%0], [%1], 16;"            \
                         :: "r"(dA + so + i_ * 2048), "l"(pa + kb_ + i_ * 65536)); \
            asm volatile("cp.async.cg.shared.global [%0], [%1], 16;"            \
                         :: "r"(dB + so + i_ * 2048), "l"(pb + kb_ + i_ * 65536)); \
        }                                                                       \
    } while (0)

    float acc[2][8][4];
#pragma unroll
    for (int i = 0; i < 2; i++)
#pragma unroll
        for (int j = 0; j < 8; j++)
#pragma unroll
            for (int c = 0; c < 4; c++) acc[i][j][c] = 0.f;

    // preamble: stages 0,1 in flight
    LOAD_STAGE(0, 0);
    asm volatile("cp.async.commit_group;" ::: "memory");
    LOAD_STAGE(1, 1);
    asm volatile("cp.async.commit_group;" ::: "memory");

    const uint32_t koff = (lane & 3) * 16;
    const uint32_t aoff = (uint32_t)(wm * 32 + (lane >> 2)) * 64 + koff;
    const uint32_t boff = (uint32_t)(wn * 64 + (lane >> 2)) * 64 + koff + 2 * PAN;

#pragma unroll
    for (int kt = 0; kt < 16; kt++) {
        const int st = kt % 3;
        asm volatile("cp.async.wait_group 1;" ::: "memory");
        __syncthreads();

        // prefetch stage kt+2 into slot (kt+2)%3 (freed by iter kt-1)
        if (kt < 14) LOAD_STAGE(kt + 2, (kt + 2) % 3);
        asm volatile("cp.async.commit_group;" ::: "memory");

        const uint32_t Astg = sb + (uint32_t)st * STGB;

#pragma unroll
        for (int s = 0; s < 2; s++) {           // two k32 panels
            const uint32_t Asb = Astg + (uint32_t)s * PAN + aoff;
            const uint32_t Bsb = Astg + (uint32_t)s * PAN + boff;

            uint32_t ah[4][4];
#pragma unroll
            for (int rdx = 0; rdx < 4; rdx++)
                asm volatile("ld.shared.v4.u32 {%0,%1,%2,%3}, [%4];"
                             : "=r"(ah[rdx][0]), "=r"(ah[rdx][1]),
                               "=r"(ah[rdx][2]), "=r"(ah[rdx][3])
                             : "r"(Asb + rdx * 512));

#pragma unroll
            for (int jh = 0; jh < 2; jh++) {
                uint32_t bh[4][4];
#pragma unroll
                for (int j = 0; j < 4; j++)
                    asm volatile("ld.shared.v4.u32 {%0,%1,%2,%3}, [%4];"
                                 : "=r"(bh[j][0]), "=r"(bh[j][1]),
                                   "=r"(bh[j][2]), "=r"(bh[j][3])
                                 : "r"(Bsb + (jh * 4 + j) * 512));
#pragma unroll
                for (int i = 0; i < 2; i++)
#pragma unroll
                    for (int j = 0; j < 4; j++)
#pragma unroll
                        for (int u = 0; u < 2; u++) {
                            const int jj = jh * 4 + j;
                            asm volatile(
                                "mma.sync.aligned.m16n8k16.row.col.f32.f16.f16.f32 "
                                "{%0,%1,%2,%3}, {%4,%5,%6,%7}, {%8,%9}, {%0,%1,%2,%3};"
                                : "+f"(acc[i][jj][0]), "+f"(acc[i][jj][1]),
                                  "+f"(acc[i][jj][2]), "+f"(acc[i][jj][3])
                                : "r"(ah[2 * i][2 * u]), "r"(ah[2 * i + 1][2 * u]),
                                  "r"(ah[2 * i][2 * u + 1]), "r"(ah[2 * i + 1][2 * u + 1]),
                                  "r"(bh[j][2 * u]), "r"(bh[j][2 * u + 1]));
                        }
            }
        }
    }
#undef LOAD_STAGE

    // Epilogue: energy = tanh(acc + dec_base[b][col]); score partial = energy . v_w
    const int b = m0 >> 11;
    float eadd[16], vv[16];
#pragma unroll
    for (int j = 0; j < 8; j++)
#pragma unroll
        for (int c = 0; c < 2; c++) {
            const int col = n0 + wn * 64 + j * 8 + (lane & 3) * 2 + c;
            eadd[j * 2 + c] = g_decb[b * ND + col];
            vv[j * 2 + c]   = vw[col];
        }

#pragma unroll
    for (int i = 0; i < 2; i++)
#pragma unroll
        for (int h = 0; h < 2; h++) {
            float p = 0.f;
#pragma unroll
            for (int j = 0; j < 8; j++)
#pragma unroll
                for (int c = 0; c < 2; c++)
                    p += fast_tanh(acc[i][j][h * 2 + c] + eadd[j * 2 + c]) * vv[j * 2 + c];
            p += __shfl_xor_sync(0xffffffffu, p, 1);
            p += __shfl_xor_sync(0xffffffffu, p, 2);
            if ((lane & 3) == 0) {
                const int row = m0 + wm * 32 + i * 16 + h * 8 + (lane >> 2);
                atomicAdd(&g_scores[row], p);
            }
        }
}

// ---------------------------------------------------------------------------
// Kernel 3: masked softmax over S per batch
// ---------------------------------------------------------------------------
__global__ void softmax_kernel(const int* __restrict__ mask,
                               float* __restrict__ out_w) {
    const int b = blockIdx.x;
    const int tid = threadIdx.x;
    __shared__ float red[256];

    float ls[8];
#pragma unroll
    for (int i = 0; i < 8; i++) {
        const int s = tid + i * 256;
        const float sc = g_scores[b * SS + s];
        ls[i] = (mask[b * SS + s] == 0) ? -1e9f : sc;
    }
    float mx = ls[0];
#pragma unroll
    for (int i = 1; i < 8; i++) mx = fmaxf(mx, ls[i]);
    red[tid] = mx;
    __syncthreads();
    for (int off = 128; off > 0; off >>= 1) {
        if (tid < off) red[tid] = fmaxf(red[tid], red[tid + off]);
        __syncthreads();
    }
    mx = red[0];
    __syncthreads();

    float ex[8];
    float sum = 0.f;
#pragma unroll
    for (int i = 0; i < 8; i++) {
        ex[i] = __expf(ls[i] - mx);
        sum += ex[i];
    }
    red[tid] = sum;
    __syncthreads();
    for (int off = 128; off > 0; off >>= 1) {
        if (tid < off) red[tid] += red[tid + off];
        __syncthreads();
    }
    const float inv = 1.f / red[0];
#pragma unroll
    for (int i = 0; i < 8; i++)
        out_w[b * SS + tid + i * 256] = ex[i] * inv;
}

// ---------------------------------------------------------------------------
// Kernel 4: context = attn_weights @ encoder_outputs (fp16 enc, fp32 accum)
// ---------------------------------------------------------------------------
__global__ void context_kernel(const float* __restrict__ w,
                               float* __restrict__ ctx) {
    const int b = blockIdx.y;
    const int ch = blockIdx.x;
    const int tid = threadIdx.x;
    __shared__ float ws[128];
    const int s0 = ch * 128;
    if (tid < 128) ws[tid] = w[b * SS + s0 + tid];
    __syncthreads();

    float ax = 0.f, ay = 0.f, az = 0.f, aw = 0.f;
    const __half* base = g_ench + ((size_t)b * SS + s0) * 1024 + tid * 4;
#pragma unroll 4
    for (int s = 0; s < 128; s++) {
        const uint2 u = *(const uint2*)(base + (size_t)s * 1024);
        const float2 f01 = __half22float2(*(const __half2*)&u.x);
        const float2 f23 = __half22float2(*(const __half2*)&u.y);
        const float wv = ws[s];
        ax += wv * f01.x;
        ay += wv * f01.y;
        az += wv * f23.x;
        aw += wv * f23.y;
    }
    float* o = ctx + b * ND + tid * 4;
    atomicAdd(o + 0, ax);
    atomicAdd(o + 1, ay);
    atomicAdd(o + 2, az);
    atomicAdd(o + 3, aw);
}

// ---------------------------------------------------------------------------
extern "C" void kernel_launch(void* const* d_in, const int* in_sizes, int n_in,
                              void* d_out, int out_size) {
    const float* dh   = (const float*)d_in[0];   // (32, 1024)
    const float* enc  = (const float*)d_in[1];   // (32, 2048, 1024)
    const int*   mask = (const int*)d_in[2];     // (32, 2048)
    const float* W    = (const float*)d_in[3];   // (2048, 1024)
    const float* ba   = (const float*)d_in[4];   // (1024,)
    const float* vw   = (const float*)d_in[5];   // (1024,)

    float* out  = (float*)d_out;
    float* ctx  = out;                 // (32, 1024)
    float* attw = out + BB * ND;       // (32, 2048)

    cudaFuncSetAttribute(score_gemm, cudaFuncAttributeMaxDynamicSharedMemorySize, GEMM_SMEM);

    pre_kernel<<<9344, 256>>>(enc, W, dh, ba, ctx);
    score_gemm<<<dim3(8, 512), 256, GEMM_SMEM>>>(vw);
    softmax_kernel<<<32, 256>>>(mask, attw);
    context_kernel<<<dim3(16, 32), 256>>>(attw, ctx);
}